// round 8
// baseline (speedup 1.0000x reference)
#include <cuda_runtime.h>

// YOLOv2 region loss — CPT=2, warp-cooperative rare path, reg-capped for
// 5 blocks/SM (single-wave residency of all 640 blocks).
// B=16, A=5, C=80, H=W=64, N_GT=50, STRIDE=16, THRESH=0.6

#define NA 5
#define NC 80
#define NGT 50
#define HW 4096
#define CH 85
#define CPT 2
#define BLK 256
#define NBLOCKS 640      // 327680 / (256*2)
#define FULL 0xffffffffu

__device__ double g_part[NBLOCKS];
__device__ unsigned int g_flag;   // zero-init; last block resets each launch

__global__ __launch_bounds__(BLK, 5) void rl_loss_kernel(
    const float* __restrict__ outp,
    const float* __restrict__ target,
    const float* __restrict__ anchors,
    float* __restrict__ out)
{
    __shared__ float4 s_box[NGT];      // x1,y1,x2,y2
    __shared__ float  s_m3sa[NGT];     // -3 * gt_area  (phase-1 key)
    __shared__ float  s_sa[NGT];       // exact gt_area (phase-2)
    __shared__ float4 s_gt[NGT];       // cx,cy,w,h
    __shared__ float  s_cls[NGT];
    __shared__ double s_red[8];
    __shared__ int    s_last;

    const int tid   = threadIdx.x;
    const int lane  = tid & 31;
    const int wid   = tid >> 5;
    const int cell0 = blockIdx.x * (BLK * CPT) + tid;   // second cell: +256
    const int ba    = cell0 >> 12;              // same for both cells (512 | 4096)
    const int b     = ba / NA;
    const int a     = ba - b * NA;
    const int hw0   = cell0 & (HW - 1);

    if (tid < NGT) {
        const float* t = target + ((size_t)b * NGT + tid) * 5;
        float cls = t[0], cx = t[1], cy = t[2], gw = t[3], gh = t[4];
        float x1 = cx - gw * 0.5f, y1 = cy - gh * 0.5f;
        float x2 = cx + gw * 0.5f, y2 = cy + gh * 0.5f;
        float sa = (x2 - x1) * (y2 - y1);
        s_box[tid]  = make_float4(x1, y1, x2, y2);
        s_m3sa[tid] = -3.0f * sa;
        s_sa[tid]   = sa;
        s_gt[tid]   = make_float4(cx, cy, gw, gh);
        s_cls[tid]  = cls;
    }
    __syncthreads();

    const float aw = anchors[2 * a];
    const float ah = anchors[2 * a + 1];
    // single 64-bit base; everything else 32-bit offsets (reg pressure)
    const float* base = outp + ((size_t)ba * CH) * HW + hw0;

    float px1[CPT], py1[CPT], px2[CPT], py2[CPT];
    float paeps[CPT], conf[CPT], mk[CPT];

    #pragma unroll
    for (int c = 0; c < CPT; c++) {
        const int o = BLK * c;
        float t0 = base[o];
        float t1 = base[o + HW];
        float t2 = base[o + 2 * HW];
        float t3 = base[o + 3 * HW];
        conf[c]  = base[o + 4 * HW];
        int hwc = hw0 + o;
        int h = hwc >> 6, w = hwc & 63;
        float sx = __fdividef(1.0f, 1.0f + __expf(-t0));
        float sy = __fdividef(1.0f, 1.0f + __expf(-t1));
        float px = (sx + (float)w) * 16.0f;
        float py = (sy + (float)h) * 16.0f;
        float pw = __expf(t2) * aw;
        float ph = __expf(t3) * ah;
        px1[c] = px - pw * 0.5f;  py1[c] = py - ph * 0.5f;
        px2[c] = px + pw * 0.5f;  py2[c] = py + ph * 0.5f;
        paeps[c] = (px2[c] - px1[c]) * (py2[c] - py1[c]) + 1e-6f;
        mk[c]    = -1e30f;
    }

    // ---- Phase 1: existence test.  iou_n > 0.6 <=> 8*I_n - 3*Sg_n > 3*(pa+eps)
#pragma unroll 5
    for (int n = 0; n < NGT; n++) {
        float4 bx = s_box[n];
        float m3  = s_m3sa[n];
        #pragma unroll
        for (int c = 0; c < CPT; c++) {
            float cw = fminf(bx.z, px2[c]) - fmaxf(bx.x, px1[c]);
            float ch = fminf(bx.w, py2[c]) - fmaxf(bx.y, py1[c]);
            float I  = fmaxf(cw, 0.0f) * fmaxf(ch, 0.0f);
            mk[c] = fmaxf(mk[c], fmaf(I, 8.0f, m3));
        }
    }

    float loss = 0.0f;

    // ---- Phase 2 (rare, warp-cooperative): exact argmax + coord/conf/class.
    #pragma unroll
    for (int c = 0; c < CPT; c++) {
        const bool msk = (mk[c] > 3.0f * paeps[c]);
        if (!msk) loss += conf[c] * conf[c];

        unsigned bal = __ballot_sync(FULL, msk);
        if (bal == 0) continue;

        while (bal) {
            const int src = __ffs(bal) - 1;
            bal &= bal - 1;

            // broadcast owner's pred box
            const float qx1 = __shfl_sync(FULL, px1[c], src);
            const float qy1 = __shfl_sync(FULL, py1[c], src);
            const float qx2 = __shfl_sync(FULL, px2[c], src);
            const float qy2 = __shfl_sync(FULL, py2[c], src);
            const float qpa = __shfl_sync(FULL, paeps[c], src);

            // lanes split 50 GTs (n = lane, n = lane+32 for lane<18);
            // cross-multiplied compare, smaller index wins ties (first argmax)
            float bI, bS; int bidx;
            {
                float4 bx = s_box[lane];
                float cw = fminf(bx.z, qx2) - fmaxf(bx.x, qx1);
                float ch = fminf(bx.w, qy2) - fmaxf(bx.y, qy1);
                bI = fmaxf(cw, 0.0f) * fmaxf(ch, 0.0f);
                bS = s_sa[lane] + qpa;
                bidx = lane;
            }
            if (lane < NGT - 32) {
                int n2 = lane + 32;
                float4 bx = s_box[n2];
                float cw = fminf(bx.z, qx2) - fmaxf(bx.x, qx1);
                float ch = fminf(bx.w, qy2) - fmaxf(bx.y, qy1);
                float I2 = fmaxf(cw, 0.0f) * fmaxf(ch, 0.0f);
                float S2 = s_sa[n2] + qpa;
                if (I2 * bS > bI * S2) { bI = I2; bS = S2; bidx = n2; }
            }
            #pragma unroll
            for (int off = 16; off; off >>= 1) {
                float oI = __shfl_down_sync(FULL, bI, off);
                float oS = __shfl_down_sync(FULL, bS, off);
                int   oi = __shfl_down_sync(FULL, bidx, off);
                float l = oI * bS, r = bI * oS;
                if (l > r || (l == r && oi < bidx)) { bI = oI; bS = oS; bidx = oi; }
            }
            bidx = __shfl_sync(FULL, bidx, 0);

            // cooperative class logsumexp for owner's cell (80 = 32+32+16);
            // pointer recomputed here (cold path) to keep hot-loop regs low
            const float* cl = base + ((wid << 5) + src - (hw0 & 31))
                            + (5 * HW + BLK * c);
            float s = __expf(cl[(size_t)lane * HW])
                    + __expf(cl[(size_t)(lane + 32) * HW]);
            if (lane < 16) s += __expf(cl[(size_t)(lane + 64) * HW]);
            #pragma unroll
            for (int off = 16; off; off >>= 1)
                s += __shfl_down_sync(FULL, s, off);
            s = __shfl_sync(FULL, s, 0);

            if (lane == src) {
                const int o = BLK * c;      // reload raw logits (L2-hot)
                float4 g = s_gt[bidx];
                float d0 = base[o]          - g.x;
                float d1 = base[o + HW]     - g.y;
                float d2 = base[o + 2 * HW] - g.z;
                float d3 = base[o + 3 * HW] - g.w;
                float dc = 5.0f * conf[c] - 5.0f;
                int idx = (int)s_cls[bidx];
                loss += d0 * d0 + d1 * d1 + d2 * d2 + d3 * d3 + dc * dc
                      + __logf(s) - cl[(size_t)idx * HW];
            }
        }
    }

    // block reduction in double
    double v = (double)loss;
    #pragma unroll
    for (int off = 16; off; off >>= 1)
        v += __shfl_down_sync(FULL, v, off);

    if (lane == 0) s_red[wid] = v;
    __syncthreads();
    if (tid < 32) {
        v = (lane < 8) ? s_red[lane] : 0.0;
        #pragma unroll
        for (int off = 4; off; off >>= 1)
            v += __shfl_down_sync(0xffu, v, off);
    }

    // last-block-reduces (single launch, graph-replay safe)
    if (tid == 0) {
        g_part[blockIdx.x] = v;
        __threadfence();
        unsigned int done = atomicAdd(&g_flag, 1u);
        s_last = (done == NBLOCKS - 1);
    }
    __syncthreads();

    if (s_last) {
        double t = 0.0;
        for (int i = tid; i < NBLOCKS; i += BLK)
            t += g_part[i];
        #pragma unroll
        for (int off = 16; off; off >>= 1)
            t += __shfl_down_sync(FULL, t, off);
        if (lane == 0) s_red[wid] = t;
        __syncthreads();
        if (tid == 0) {
            double tot = 0.0;
            #pragma unroll
            for (int i = 0; i < 8; i++) tot += s_red[i];
            out[0] = (float)tot;
            atomicExch(&g_flag, 0u);
        }
    }
}

extern "C" void kernel_launch(void* const* d_in, const int* in_sizes, int n_in,
                              void* d_out, int out_size)
{
    const float* outp    = (const float*)d_in[0];
    const float* target  = (const float*)d_in[1];
    const float* anchors = (const float*)d_in[2];
    float* out = (float*)d_out;

    rl_loss_kernel<<<NBLOCKS, BLK>>>(outp, target, anchors, out);
}

// round 9
// speedup vs baseline: 1.2931x; 1.2931x over previous
#include <cuda_runtime.h>

// YOLOv2 region loss — CPT=2 with 2-row×32-col warp tiles + per-warp geometric
// GT prefilter (necessary condition: GT box must contain some pred center in
// the warp's strip), warp-cooperative exact rare path.
// B=16, A=5, C=80, H=W=64, N_GT=50, STRIDE=16, THRESH=0.6

#define NA 5
#define NC 80
#define NGT 50
#define HW 4096
#define CH 85
#define BLK 256
#define NBLOCKS 640      // 327680 / 512
#define FULL 0xffffffffu

__device__ double g_part[NBLOCKS];
__device__ unsigned int g_flag;   // zero-init; last block resets each launch

__global__ __launch_bounds__(BLK, 5) void rl_loss_kernel(
    const float* __restrict__ outp,
    const float* __restrict__ target,
    const float* __restrict__ anchors,
    float* __restrict__ out)
{
    __shared__ float4 s_box[NGT];      // x1,y1,x2,y2
    __shared__ float  s_m3sa[NGT];     // -3 * gt_area  (phase-1 key)
    __shared__ float  s_sa[NGT];       // exact gt_area (phase-2)
    __shared__ float4 s_gt[NGT];       // cx,cy,w,h
    __shared__ float  s_cls[NGT];
    __shared__ double s_red[8];
    __shared__ int    s_last;

    const int tid  = threadIdx.x;
    const int lane = tid & 31;
    const int wid  = tid >> 5;

    // block = 512 consecutive cells of one (b,a); warp = 2-row x 32-col tile
    const int cellblk = blockIdx.x * 512;
    const int ba      = cellblk >> 12;          // same for whole block
    const int b       = ba / NA;
    const int a       = ba - b * NA;
    const int hwbase  = cellblk & (HW - 1);
    const int oW      = ((wid >> 1) << 7) + ((wid & 1) << 5);  // warp tile offset
    const int oA      = oW + lane;              // cell A; cell B = oA + 64

    if (tid < NGT) {
        const float* t = target + ((size_t)b * NGT + tid) * 5;
        float cls = t[0], cx = t[1], cy = t[2], gw = t[3], gh = t[4];
        float x1 = cx - gw * 0.5f, y1 = cy - gh * 0.5f;
        float x2 = cx + gw * 0.5f, y2 = cy + gh * 0.5f;
        float sa = (x2 - x1) * (y2 - y1);
        s_box[tid]  = make_float4(x1, y1, x2, y2);
        s_m3sa[tid] = -3.0f * sa;
        s_sa[tid]   = sa;
        s_gt[tid]   = make_float4(cx, cy, gw, gh);
        s_cls[tid]  = cls;
    }
    __syncthreads();

    const float aw = anchors[2 * a];
    const float ah = anchors[2 * a + 1];
    const float* base = outp + ((size_t)ba * CH) * HW + hwbase;

    float px1[2], py1[2], px2[2], py2[2], paeps[2], conf[2], mk[2];

    #pragma unroll
    for (int c = 0; c < 2; c++) {
        const int o = oA + 64 * c;
        float t0 = base[o];
        float t1 = base[o + HW];
        float t2 = base[o + 2 * HW];
        float t3 = base[o + 3 * HW];
        conf[c]  = base[o + 4 * HW];
        int hwc = hwbase + o;
        int h = hwc >> 6, w = hwc & 63;
        float sx = __fdividef(1.0f, 1.0f + __expf(-t0));
        float sy = __fdividef(1.0f, 1.0f + __expf(-t1));
        float px = (sx + (float)w) * 16.0f;
        float py = (sy + (float)h) * 16.0f;
        float pw = __expf(t2) * aw;
        float ph = __expf(t3) * ah;
        px1[c] = px - pw * 0.5f;  py1[c] = py - ph * 0.5f;
        px2[c] = px + pw * 0.5f;  py2[c] = py + ph * 0.5f;
        paeps[c] = (px2[c] - px1[c]) * (py2[c] - py1[c]) + 1e-6f;
        mk[c]    = -1e30f;
    }

    // ---- Per-warp GT prefilter.  iou>0.6 requires the GT box to contain the
    // pred center; pred centers of this warp lie in x:(xlo,xhi), y:(ylo,yhi).
    // 1px slack absorbs fp rounding (proof margin is 0.1*gw >= 1px).
    unsigned b0, b1;
    {
        const float xlo = (float)(((wid & 1) << 9)) - 1.0f;           // 512*colhalf
        const float xhi = xlo + 514.0f;
        const float ylo = (float)(((hwbase >> 6) + ((wid >> 1) << 1)) << 4) - 1.0f;
        const float yhi = ylo + 34.0f;
        float4 bx = s_box[lane];
        bool p = (bx.z > xlo) & (bx.x < xhi) & (bx.w > ylo) & (bx.y < yhi);
        b0 = __ballot_sync(FULL, p);
        bool q = false;
        if (lane < NGT - 32) {
            float4 b2 = s_box[lane + 32];
            q = (b2.z > xlo) & (b2.x < xhi) & (b2.w > ylo) & (b2.y < yhi);
        }
        b1 = __ballot_sync(FULL, q);
    }

    // ---- Phase 1 over surviving GTs only: iou_n>0.6 <=> 8*I_n-3*Sg_n > 3*(pa+eps)
    #pragma unroll
    for (int word = 0; word < 2; word++) {
        unsigned bb = word ? b1 : b0;
        const int boff = word << 5;
        while (bb) {
            int n = (__ffs(bb) - 1) + boff;
            bb &= bb - 1;
            float4 bx = s_box[n];
            float m3  = s_m3sa[n];
            #pragma unroll
            for (int c = 0; c < 2; c++) {
                float cw = fminf(bx.z, px2[c]) - fmaxf(bx.x, px1[c]);
                float ch = fminf(bx.w, py2[c]) - fmaxf(bx.y, py1[c]);
                float I  = fmaxf(cw, 0.0f) * fmaxf(ch, 0.0f);
                mk[c] = fmaxf(mk[c], fmaf(I, 8.0f, m3));
            }
        }
    }

    float loss = 0.0f;

    // ---- Phase 2 (rare, warp-cooperative): exact argmax over ALL 50 GTs,
    // coord/conf loss + cooperative class logsumexp.
    #pragma unroll
    for (int c = 0; c < 2; c++) {
        const bool msk = (mk[c] > 3.0f * paeps[c]);
        if (!msk) loss += conf[c] * conf[c];

        unsigned bal = __ballot_sync(FULL, msk);
        while (bal) {
            const int src = __ffs(bal) - 1;
            bal &= bal - 1;

            const float qx1 = __shfl_sync(FULL, px1[c], src);
            const float qy1 = __shfl_sync(FULL, py1[c], src);
            const float qx2 = __shfl_sync(FULL, px2[c], src);
            const float qy2 = __shfl_sync(FULL, py2[c], src);
            const float qpa = __shfl_sync(FULL, paeps[c], src);

            // lanes split 50 GTs; cross-multiplied compare (monotone-equiv to
            // iou = I/(S-I)); smaller index wins ties = first-occurrence argmax
            float bI, bS; int bidx;
            {
                float4 bx = s_box[lane];
                float cw = fminf(bx.z, qx2) - fmaxf(bx.x, qx1);
                float ch = fminf(bx.w, qy2) - fmaxf(bx.y, qy1);
                bI = fmaxf(cw, 0.0f) * fmaxf(ch, 0.0f);
                bS = s_sa[lane] + qpa;
                bidx = lane;
            }
            if (lane < NGT - 32) {
                int n2 = lane + 32;
                float4 bx = s_box[n2];
                float cw = fminf(bx.z, qx2) - fmaxf(bx.x, qx1);
                float ch = fminf(bx.w, qy2) - fmaxf(bx.y, qy1);
                float I2 = fmaxf(cw, 0.0f) * fmaxf(ch, 0.0f);
                float S2 = s_sa[n2] + qpa;
                if (I2 * bS > bI * S2) { bI = I2; bS = S2; bidx = n2; }
            }
            #pragma unroll
            for (int off = 16; off; off >>= 1) {
                float oI = __shfl_down_sync(FULL, bI, off);
                float oS = __shfl_down_sync(FULL, bS, off);
                int   oi = __shfl_down_sync(FULL, bidx, off);
                float l = oI * bS, r = bI * oS;
                if (l > r || (l == r && oi < bidx)) { bI = oI; bS = oS; bidx = oi; }
            }
            bidx = __shfl_sync(FULL, bidx, 0);

            // cooperative class logsumexp for owner's cell (80 = 32+32+16)
            const float* cl = base + (oW + src + 64 * c) + 5 * HW;
            float s = __expf(cl[(size_t)lane * HW])
                    + __expf(cl[(size_t)(lane + 32) * HW]);
            if (lane < 16) s += __expf(cl[(size_t)(lane + 64) * HW]);
            #pragma unroll
            for (int off = 16; off; off >>= 1)
                s += __shfl_down_sync(FULL, s, off);
            s = __shfl_sync(FULL, s, 0);

            if (lane == src) {
                const int o = oA + 64 * c;      // reload raw logits (L2-hot)
                float4 g = s_gt[bidx];
                float d0 = base[o]          - g.x;
                float d1 = base[o + HW]     - g.y;
                float d2 = base[o + 2 * HW] - g.z;
                float d3 = base[o + 3 * HW] - g.w;
                float dc = 5.0f * conf[c] - 5.0f;
                int idx = (int)s_cls[bidx];
                loss += d0 * d0 + d1 * d1 + d2 * d2 + d3 * d3 + dc * dc
                      + __logf(s) - cl[(size_t)idx * HW];
            }
        }
    }

    // block reduction in double
    double v = (double)loss;
    #pragma unroll
    for (int off = 16; off; off >>= 1)
        v += __shfl_down_sync(FULL, v, off);

    if (lane == 0) s_red[wid] = v;
    __syncthreads();
    if (tid < 32) {
        v = (lane < 8) ? s_red[lane] : 0.0;
        #pragma unroll
        for (int off = 4; off; off >>= 1)
            v += __shfl_down_sync(0xffu, v, off);
    }

    // last-block-reduces (single launch, graph-replay safe)
    if (tid == 0) {
        g_part[blockIdx.x] = v;
        __threadfence();
        unsigned int done = atomicAdd(&g_flag, 1u);
        s_last = (done == NBLOCKS - 1);
    }
    __syncthreads();

    if (s_last) {
        double t = 0.0;
        for (int i = tid; i < NBLOCKS; i += BLK)
            t += g_part[i];
        #pragma unroll
        for (int off = 16; off; off >>= 1)
            t += __shfl_down_sync(FULL, t, off);
        if (lane == 0) s_red[wid] = t;
        __syncthreads();
        if (tid == 0) {
            double tot = 0.0;
            #pragma unroll
            for (int i = 0; i < 8; i++) tot += s_red[i];
            out[0] = (float)tot;
            atomicExch(&g_flag, 0u);
        }
    }
}

extern "C" void kernel_launch(void* const* d_in, const int* in_sizes, int n_in,
                              void* d_out, int out_size)
{
    const float* outp    = (const float*)d_in[0];
    const float* target  = (const float*)d_in[1];
    const float* anchors = (const float*)d_in[2];
    float* out = (float*)d_out;

    rl_loss_kernel<<<NBLOCKS, BLK>>>(outp, target, anchors, out);
}